// round 14
// baseline (speedup 1.0000x reference)
#include <cuda_runtime.h>
#include <math.h>

#define N_   8
#define C_   64
#define H_   256
#define W_   256
#define K2_  9
#define NBLK 512
#define QELEMS (H_ * W_ / 4)

// scratch (no cudaMalloc allowed); all counters monotonic => graph-replay safe
__device__ float g_part[N_ * C_ * 4];            // quarter-plane raw sums
__device__ unsigned int g_done[N_];              // pool completions per sample
__device__ unsigned int g_epoch_blk[NBLK];       // per-block replay counter

// ---------------------------------------------------------------------------
// Stencil for one 64-row x 256-col tile. Each warp = ONE 8-row full-width
// band (8 cols/lane): reflect edges resolve inside edge lanes, no scalar
// edge loads. Rolling 3x10 window + one pending raw row (distance-1 prefetch)
// keeps next row's 2 LDG.128 in flight during current-row compute.
// Read amplification 10/8 = 1.25x (vs 1.5x for 4-row bands).
// ---------------------------------------------------------------------------
__device__ __forceinline__ void stencil_tile(
        const float* __restrict__ x, float* __restrict__ out,
        int plane, int tile, int warp, int lane,
        const float* __restrict__ wlfk, float A, float Bc, float lh1) {
    const size_t plane_off = (size_t)plane * (H_ * W_);
    const float* xp = x + plane_off;
    const int y0 = tile * 64 + warp * 8;     // first output row of this warp

    const float w0 = wlfk[0], w1 = wlfk[1], w2 = wlfk[2];
    const float w3 = wlfk[3], w4 = wlfk[4], w5 = wlfk[5];
    const float w6 = wlfk[6], w7 = wlfk[7], w8 = wlfk[8];

    #define RAW(GR, L, R) do {                                             \
        int _g = (GR);                                                     \
        _g = _g < 0 ? 1 : (_g >= H_ ? 2 * H_ - 2 - _g : _g);               \
        const float4* _p = (const float4*)(xp + (size_t)_g * W_);          \
        (L) = __ldg(&_p[2 * lane]);                                        \
        (R) = __ldg(&_p[2 * lane + 1]);                                    \
    } while (0)

    #define FIN(L, R, D) do {                                              \
        float _lf = __shfl_up_sync(0xffffffffu, (R).w, 1);                 \
        float _rt = __shfl_down_sync(0xffffffffu, (L).x, 1);               \
        if (lane == 0)  _lf = (L).y;   /* reflect col -1 -> col 1   */     \
        if (lane == 31) _rt = (R).z;   /* reflect col 256 -> col 254 */    \
        (D)[0] = _lf;                                                      \
        (D)[1] = (L).x; (D)[2] = (L).y; (D)[3] = (L).z; (D)[4] = (L).w;    \
        (D)[5] = (R).x; (D)[6] = (R).y; (D)[7] = (R).z; (D)[8] = (R).w;    \
        (D)[9] = _rt;                                                      \
    } while (0)

    float win[3][10];
    float4 aL, aR, pL, pR;

    RAW(y0 - 1, aL, aR);                 // row s=0
    RAW(y0,     pL, pR);                 // row s=1 (pending)
    FIN(aL, aR, win[0]);
    RAW(y0 + 1, aL, aR);                 // row s=2 -> becomes pending below
    FIN(pL, pR, win[1]);
    pL = aL; pR = aR;                    // pending = row s=2

    float* ob = out + plane_off + (size_t)y0 * W_ + 8 * lane;

    #pragma unroll
    for (int k = 0; k < 8; ++k) {
        // consume pending row s=k+2; prefetch row s=k+3
        float4 cL = pL, cR = pR;
        if (k < 7) RAW(y0 + 2 + k, pL, pR);
        FIN(cL, cR, win[(k + 2) % 3]);

        const float* t0 = win[k % 3];
        const float* t1 = win[(k + 1) % 3];
        const float* t2 = win[(k + 2) % 3];
        float o[8];
        #pragma unroll
        for (int j = 0; j < 8; ++j) {
            float acc;
            acc = w0 * t0[j];
            acc = fmaf(w1, t0[j + 1], acc);
            acc = fmaf(w2, t0[j + 2], acc);
            acc = fmaf(w3, t1[j],     acc);
            acc = fmaf(w4, t1[j + 1], acc);
            acc = fmaf(w5, t1[j + 2], acc);
            acc = fmaf(w6, t2[j],     acc);
            acc = fmaf(w7, t2[j + 1], acc);
            acc = fmaf(w8, t2[j + 2], acc);
            o[j] = fmaf(acc, A, fmaf(t1[j + 1], lh1, Bc));
        }
        float4* op = (float4*)(ob + (size_t)k * W_);
        __stcs(op,     make_float4(o[0], o[1], o[2], o[3]));
        __stcs(op + 1, make_float4(o[4], o[5], o[6], o[7]));
    }
    #undef RAW
    #undef FIN
}

// ---------------------------------------------------------------------------
// Group-decoupled pipeline: block group g (64 blocks, all co-resident) owns
// sample g. Pool quarters k=0..3, group-local wait, stencil LIFO k=3..0.
// ---------------------------------------------------------------------------
__global__ __launch_bounds__(256, 4) void fused_kernel(
        const float* __restrict__ x,
        const float* __restrict__ conv_w,
        const float* __restrict__ bn_gamma,
        const float* __restrict__ bn_beta,
        const float* __restrict__ bn_mean,
        const float* __restrict__ bn_var,
        const float* __restrict__ lamb_l,
        const float* __restrict__ lamb_h,
        const float* __restrict__ inside_all,
        float* __restrict__ out) {
    const int b    = blockIdx.x;
    const int g    = b >> 6;          // sample / group id
    const int r    = b & 63;          // rank within group
    const int tid  = threadIdx.x;
    const int warp = tid >> 5;
    const int lane = tid & 31;

    __shared__ float ws[8];
    __shared__ float ps[C_];
    __shared__ float wlf[4][K2_];
    __shared__ float cst[4][3];       // A, Bc, lh1 per k

    unsigned int target = 0;
    if (tid == 0)
        target = (atomicAdd(&g_epoch_blk[b], 1u) + 1u) * 256u;

    // ---- pool: 4 quarter-plane items of sample g (k = 0..3) ----------------
    #pragma unroll 1
    for (int k = 0; k < 4; ++k) {
        const int item = g * 256 + r + 64 * k;
        const float4* xv = (const float4*)(x + (size_t)item * QELEMS);
        float s = 0.f;
        #pragma unroll
        for (int i = 0; i < 16; ++i) {
            float4 v = __ldg(&xv[tid + i * 256]);
            s += (v.x + v.y) + (v.z + v.w);
        }
        #pragma unroll
        for (int o = 16; o; o >>= 1) s += __shfl_down_sync(0xffffffffu, s, o);
        if (lane == 0) ws[warp] = s;
        __syncthreads();
        if (tid == 0)
            g_part[item] = ws[0] + ws[1] + ws[2] + ws[3]
                         + ws[4] + ws[5] + ws[6] + ws[7];
        __syncthreads();
    }

    // ---- group-local release + wait (64 blocks only) -----------------------
    if (tid == 0) {
        __threadfence();
        atomicAdd(&g_done[g], 4u);
        while (*((volatile unsigned int*)&g_done[g]) < target)
            __nanosleep(32);
    }
    __syncthreads();
    __threadfence();

    // ---- lf weights + per-channel constants (all 4 k at once) --------------
    if (tid < C_) {
        const float* p = g_part + (g * C_ + tid) * 4;
        ps[tid] = (__ldcg(p) + __ldcg(p + 1) + __ldcg(p + 2) + __ldcg(p + 3))
                  * (1.f / (H_ * W_));
    }
    __syncthreads();
    if (tid < 36) {
        const int k  = tid / 9;
        const int t9 = tid - 9 * k;
        const int c  = (r >> 2) + 16 * k;
        const int jj = (c >> 3) * K2_ + t9;
        const float* wv = conv_w + jj * C_;
        float acc = 0.f;
        #pragma unroll
        for (int cc = 0; cc < C_; ++cc) acc = fmaf(ps[cc], wv[cc], acc);
        const float inv = rsqrtf(bn_var[jj] + 1e-5f);
        const float v = (acc - bn_mean[jj]) * (bn_gamma[jj] * inv) + bn_beta[jj];
        wlf[k][t9] = tanhf(v);
        if (t9 == 0) {
            const float ll  = __ldg(lamb_l + c);
            const float ia  = __ldg(inside_all + c);
            cst[k][0] = (ia + 1.f) * ll;          // A
            cst[k][1] = -ia * ps[c] * ll;         // Bc
            cst[k][2] = __ldg(lamb_h + c) + 1.f;  // lh1
        }
    }
    __syncthreads();

    // ---- 4 stencil tiles, LIFO over pooled quarters (k = 3..0) -------------
    const int tile = r & 3;
    #pragma unroll 1
    for (int k = 3; k >= 0; --k) {
        const int c     = (r >> 2) + 16 * k;
        const int plane = g * C_ + c;
        stencil_tile(x, out, plane, tile, warp, lane,
                     wlf[k], cst[k][0], cst[k][1], cst[k][2]);
    }
}

// ---------------------------------------------------------------------------
extern "C" void kernel_launch(void* const* d_in, const int* in_sizes, int n_in,
                              void* d_out, int out_size) {
    const float* x          = (const float*)d_in[0];
    const float* conv_w     = (const float*)d_in[1];
    const float* bn_gamma   = (const float*)d_in[2];
    const float* bn_beta    = (const float*)d_in[3];
    const float* bn_mean    = (const float*)d_in[4];
    const float* bn_var     = (const float*)d_in[5];
    const float* lamb_l     = (const float*)d_in[6];
    const float* lamb_h     = (const float*)d_in[7];
    const float* inside_all = (const float*)d_in[8];
    float* out = (float*)d_out;

    fused_kernel<<<NBLK, 256>>>(x, conv_w, bn_gamma, bn_beta, bn_mean, bn_var,
                                lamb_l, lamb_h, inside_all, out);
}

// round 15
// speedup vs baseline: 1.1161x; 1.1161x over previous
#include <cuda_runtime.h>
#include <math.h>

#define N_   8
#define C_   64
#define H_   256
#define W_   256
#define K2_  9
#define NBLK 512
#define QELEMS (H_ * W_ / 4)

// scratch (no cudaMalloc allowed); all counters monotonic => graph-replay safe
__device__ float g_part[N_ * C_ * 4];            // quarter-plane raw sums
__device__ unsigned int g_done[N_];              // pool completions per sample
__device__ unsigned int g_epoch_blk[NBLK];       // per-block replay counter

// ---------------------------------------------------------------------------
// Stencil for one 64-row x 256-col tile. Each warp: 4 tasks; a task is a
// 4-row x 128-col half-band. All 6 input rows preloaded (12 independent LDG)
// before SHFL/compute. Reflect padding resolved in-register.
// Stores are write-through (__stwt): out never allocates L2 lines, so x stays
// resident and the LTS path carries fewer bytes.
// ---------------------------------------------------------------------------
__device__ __forceinline__ void stencil_tile(
        const float* __restrict__ x, float* __restrict__ out,
        int plane, int tile, int warp, int lane,
        const float* wlf, float A, float Bc, float lh1) {
    const size_t plane_off = (size_t)plane * (H_ * W_);
    const float* xp = x + plane_off;

    const float w0 = wlf[0], w1 = wlf[1], w2 = wlf[2];
    const float w3 = wlf[3], w4 = wlf[4], w5 = wlf[5];
    const float w6 = wlf[6], w7 = wlf[7], w8 = wlf[8];

    #pragma unroll 1
    for (int i = 0; i < 4; ++i) {
        const int T    = warp * 4 + i;      // 0..31
        const int band = T >> 1;            // 0..15 -> 4-row band
        const int half = T & 1;             // 128-col half
        const int y0   = tile * 64 + band * 4;
        const int cb   = half * 128 + lane * 4;

        float win[6][6];
        #pragma unroll
        for (int r = 0; r < 6; ++r) {
            int g = y0 - 1 + r;
            g = g < 0 ? 1 : (g >= H_ ? 2 * H_ - 2 - g : g);
            const float* rp = xp + (size_t)g * W_;
            float4 v = __ldg((const float4*)(rp + cb));
            float  e = __ldg(rp + (half ? 127 : 128));   // uniform boundary scalar
            float lf = __shfl_up_sync(0xffffffffu, v.w, 1);
            float rt = __shfl_down_sync(0xffffffffu, v.x, 1);
            if (half == 0) {
                if (lane == 0)  lf = v.y;   // reflect col -1 -> col 1
                if (lane == 31) rt = e;     // col 128 from other half
            } else {
                if (lane == 0)  lf = e;     // col 127 from other half
                if (lane == 31) rt = v.z;   // reflect col 256 -> col 254
            }
            win[r][0] = lf;
            win[r][1] = v.x; win[r][2] = v.y; win[r][3] = v.z; win[r][4] = v.w;
            win[r][5] = rt;
        }

        float* ob = out + plane_off + (size_t)y0 * W_ + cb;
        #pragma unroll
        for (int k = 0; k < 4; ++k) {
            float o[4];
            #pragma unroll
            for (int j = 0; j < 4; ++j) {
                float acc;
                acc = w0 * win[k][j];
                acc = fmaf(w1, win[k][j + 1], acc);
                acc = fmaf(w2, win[k][j + 2], acc);
                acc = fmaf(w3, win[k + 1][j],     acc);
                acc = fmaf(w4, win[k + 1][j + 1], acc);
                acc = fmaf(w5, win[k + 1][j + 2], acc);
                acc = fmaf(w6, win[k + 2][j],     acc);
                acc = fmaf(w7, win[k + 2][j + 1], acc);
                acc = fmaf(w8, win[k + 2][j + 2], acc);
                o[j] = fmaf(acc, A, fmaf(win[k + 1][j + 1], lh1, Bc));
            }
            __stwt((float4*)(ob + (size_t)k * W_),
                   make_float4(o[0], o[1], o[2], o[3]));
        }
    }
}

// ---------------------------------------------------------------------------
// Group-decoupled pipeline: block group g (64 blocks, all co-resident) owns
// sample g. Pool quarters k=0..3, group-local wait, stencil LIFO k=3..0.
// ---------------------------------------------------------------------------
__global__ __launch_bounds__(256, 4) void fused_kernel(
        const float* __restrict__ x,
        const float* __restrict__ conv_w,
        const float* __restrict__ bn_gamma,
        const float* __restrict__ bn_beta,
        const float* __restrict__ bn_mean,
        const float* __restrict__ bn_var,
        const float* __restrict__ lamb_l,
        const float* __restrict__ lamb_h,
        const float* __restrict__ inside_all,
        float* __restrict__ out) {
    const int b    = blockIdx.x;
    const int g    = b >> 6;          // sample / group id
    const int r    = b & 63;          // rank within group
    const int tid  = threadIdx.x;
    const int warp = tid >> 5;
    const int lane = tid & 31;

    __shared__ float ws[8];
    __shared__ float ps[C_];
    __shared__ float wlf[4][K2_];
    __shared__ float cst[4][3];       // A, Bc, lh1 per k

    unsigned int target = 0;
    if (tid == 0)
        target = (atomicAdd(&g_epoch_blk[b], 1u) + 1u) * 256u;

    // ---- pool: 4 quarter-plane items of sample g (k = 0..3) ----------------
    #pragma unroll 1
    for (int k = 0; k < 4; ++k) {
        const int item = g * 256 + r + 64 * k;
        const float4* xv = (const float4*)(x + (size_t)item * QELEMS);
        float s = 0.f;
        #pragma unroll
        for (int i = 0; i < 16; ++i) {
            float4 v = __ldg(&xv[tid + i * 256]);
            s += (v.x + v.y) + (v.z + v.w);
        }
        #pragma unroll
        for (int o = 16; o; o >>= 1) s += __shfl_down_sync(0xffffffffu, s, o);
        if (lane == 0) ws[warp] = s;
        __syncthreads();
        if (tid == 0)
            g_part[item] = ws[0] + ws[1] + ws[2] + ws[3]
                         + ws[4] + ws[5] + ws[6] + ws[7];
        __syncthreads();
    }

    // ---- group-local release + wait (64 blocks only) -----------------------
    if (tid == 0) {
        __threadfence();
        atomicAdd(&g_done[g], 4u);
        while (*((volatile unsigned int*)&g_done[g]) < target)
            __nanosleep(32);
    }
    __syncthreads();
    __threadfence();

    // ---- lf weights + per-channel constants (all 4 k at once) --------------
    if (tid < C_) {
        const float* p = g_part + (g * C_ + tid) * 4;
        ps[tid] = (__ldcg(p) + __ldcg(p + 1) + __ldcg(p + 2) + __ldcg(p + 3))
                  * (1.f / (H_ * W_));
    }
    __syncthreads();
    if (tid < 36) {
        const int k  = tid / 9;
        const int t9 = tid - 9 * k;
        const int c  = (r >> 2) + 16 * k;
        const int jj = (c >> 3) * K2_ + t9;
        const float* wv = conv_w + jj * C_;
        float acc = 0.f;
        #pragma unroll
        for (int cc = 0; cc < C_; ++cc) acc = fmaf(ps[cc], wv[cc], acc);
        const float inv = rsqrtf(bn_var[jj] + 1e-5f);
        const float v = (acc - bn_mean[jj]) * (bn_gamma[jj] * inv) + bn_beta[jj];
        wlf[k][t9] = tanhf(v);
        if (t9 == 0) {
            const float ll  = __ldg(lamb_l + c);
            const float ia  = __ldg(inside_all + c);
            cst[k][0] = (ia + 1.f) * ll;          // A
            cst[k][1] = -ia * ps[c] * ll;         // Bc
            cst[k][2] = __ldg(lamb_h + c) + 1.f;  // lh1
        }
    }
    __syncthreads();

    // ---- 4 stencil tiles, LIFO over pooled quarters (k = 3..0) -------------
    const int tile = r & 3;
    #pragma unroll 1
    for (int k = 3; k >= 0; --k) {
        const int c     = (r >> 2) + 16 * k;
        const int plane = g * C_ + c;
        stencil_tile(x, out, plane, tile, warp, lane,
                     wlf[k], cst[k][0], cst[k][1], cst[k][2]);
    }
}

// ---------------------------------------------------------------------------
extern "C" void kernel_launch(void* const* d_in, const int* in_sizes, int n_in,
                              void* d_out, int out_size) {
    const float* x          = (const float*)d_in[0];
    const float* conv_w     = (const float*)d_in[1];
    const float* bn_gamma   = (const float*)d_in[2];
    const float* bn_beta    = (const float*)d_in[3];
    const float* bn_mean    = (const float*)d_in[4];
    const float* bn_var     = (const float*)d_in[5];
    const float* lamb_l     = (const float*)d_in[6];
    const float* lamb_h     = (const float*)d_in[7];
    const float* inside_all = (const float*)d_in[8];
    float* out = (float*)d_out;

    fused_kernel<<<NBLK, 256>>>(x, conv_w, bn_gamma, bn_beta, bn_mean, bn_var,
                                lamb_l, lamb_h, inside_all, out);
}

// round 17
// speedup vs baseline: 1.1208x; 1.0042x over previous
#include <cuda_runtime.h>
#include <math.h>
#include <stdint.h>

#define N_   8
#define C_   64
#define H_   256
#define W_   256
#define K2_  9
#define NBLK 512
#define QELEMS (H_ * W_ / 4)

// scratch (no cudaMalloc allowed); all counters monotonic => graph-replay safe
__device__ float g_part[N_ * C_ * 4];            // quarter-plane raw sums
__device__ unsigned int g_done[N_];              // pool completions per sample
__device__ unsigned int g_epoch_blk[NBLK];       // per-block replay counter

// ---- evict_last policy loads: x owns the L2; __stcs stores yield to it -----
__device__ __forceinline__ uint64_t mk_evict_last_policy() {
    uint64_t pol;
    asm("createpolicy.fractional.L2::evict_last.b64 %0, 1.0;" : "=l"(pol));
    return pol;
}
__device__ __forceinline__ float4 ldg_el4(const float4* p, uint64_t pol) {
    float4 v;
    asm("ld.global.nc.L2::cache_hint.v4.f32 {%0,%1,%2,%3}, [%4], %5;"
        : "=f"(v.x), "=f"(v.y), "=f"(v.z), "=f"(v.w) : "l"(p), "l"(pol));
    return v;
}
__device__ __forceinline__ float ldg_el1(const float* p, uint64_t pol) {
    float v;
    asm("ld.global.nc.L2::cache_hint.f32 %0, [%1], %2;"
        : "=f"(v) : "l"(p), "l"(pol));
    return v;
}

// ---------------------------------------------------------------------------
// Stencil for one 64-row x 256-col tile. Each warp: 4 tasks; a task is a
// 4-row x 128-col half-band. All 6 input rows preloaded (12 independent LDG)
// before SHFL/compute. Reflect padding resolved in-register.
// ---------------------------------------------------------------------------
__device__ __forceinline__ void stencil_tile(
        const float* __restrict__ x, float* __restrict__ out,
        int plane, int tile, int warp, int lane, uint64_t pol,
        const float* wlf, float A, float Bc, float lh1) {
    const size_t plane_off = (size_t)plane * (H_ * W_);
    const float* xp = x + plane_off;

    const float w0 = wlf[0], w1 = wlf[1], w2 = wlf[2];
    const float w3 = wlf[3], w4 = wlf[4], w5 = wlf[5];
    const float w6 = wlf[6], w7 = wlf[7], w8 = wlf[8];

    #pragma unroll 1
    for (int i = 0; i < 4; ++i) {
        const int T    = warp * 4 + i;      // 0..31
        const int band = T >> 1;            // 0..15 -> 4-row band
        const int half = T & 1;             // 128-col half
        const int y0   = tile * 64 + band * 4;
        const int cb   = half * 128 + lane * 4;

        float win[6][6];
        #pragma unroll
        for (int r = 0; r < 6; ++r) {
            int g = y0 - 1 + r;
            g = g < 0 ? 1 : (g >= H_ ? 2 * H_ - 2 - g : g);
            const float* rp = xp + (size_t)g * W_;
            float4 v = ldg_el4((const float4*)(rp + cb), pol);
            float  e = ldg_el1(rp + (half ? 127 : 128), pol);  // boundary scalar
            float lf = __shfl_up_sync(0xffffffffu, v.w, 1);
            float rt = __shfl_down_sync(0xffffffffu, v.x, 1);
            if (half == 0) {
                if (lane == 0)  lf = v.y;   // reflect col -1 -> col 1
                if (lane == 31) rt = e;     // col 128 from other half
            } else {
                if (lane == 0)  lf = e;     // col 127 from other half
                if (lane == 31) rt = v.z;   // reflect col 256 -> col 254
            }
            win[r][0] = lf;
            win[r][1] = v.x; win[r][2] = v.y; win[r][3] = v.z; win[r][4] = v.w;
            win[r][5] = rt;
        }

        float* ob = out + plane_off + (size_t)y0 * W_ + cb;
        #pragma unroll
        for (int k = 0; k < 4; ++k) {
            float o[4];
            #pragma unroll
            for (int j = 0; j < 4; ++j) {
                float acc;
                acc = w0 * win[k][j];
                acc = fmaf(w1, win[k][j + 1], acc);
                acc = fmaf(w2, win[k][j + 2], acc);
                acc = fmaf(w3, win[k + 1][j],     acc);
                acc = fmaf(w4, win[k + 1][j + 1], acc);
                acc = fmaf(w5, win[k + 1][j + 2], acc);
                acc = fmaf(w6, win[k + 2][j],     acc);
                acc = fmaf(w7, win[k + 2][j + 1], acc);
                acc = fmaf(w8, win[k + 2][j + 2], acc);
                o[j] = fmaf(acc, A, fmaf(win[k + 1][j + 1], lh1, Bc));
            }
            __stcs((float4*)(ob + (size_t)k * W_),
                   make_float4(o[0], o[1], o[2], o[3]));
        }
    }
}

// ---------------------------------------------------------------------------
// Group-decoupled pipeline: block group g (64 blocks, all co-resident) owns
// sample g. Pool quarters k=0..3, group-local wait, stencil LIFO k=3..0.
// ---------------------------------------------------------------------------
__global__ __launch_bounds__(256, 4) void fused_kernel(
        const float* __restrict__ x,
        const float* __restrict__ conv_w,
        const float* __restrict__ bn_gamma,
        const float* __restrict__ bn_beta,
        const float* __restrict__ bn_mean,
        const float* __restrict__ bn_var,
        const float* __restrict__ lamb_l,
        const float* __restrict__ lamb_h,
        const float* __restrict__ inside_all,
        float* __restrict__ out) {
    const int b    = blockIdx.x;
    const int g    = b >> 6;          // sample / group id
    const int r    = b & 63;          // rank within group
    const int tid  = threadIdx.x;
    const int warp = tid >> 5;
    const int lane = tid & 31;

    __shared__ float ws[8];
    __shared__ float ps[C_];
    __shared__ float wlf[4][K2_];
    __shared__ float cst[4][3];       // A, Bc, lh1 per k

    const uint64_t pol = mk_evict_last_policy();

    unsigned int target = 0;
    if (tid == 0)
        target = (atomicAdd(&g_epoch_blk[b], 1u) + 1u) * 256u;

    // ---- pool: 4 quarter-plane items of sample g (k = 0..3) ----------------
    #pragma unroll 1
    for (int k = 0; k < 4; ++k) {
        const int item = g * 256 + r + 64 * k;
        const float4* xv = (const float4*)(x + (size_t)item * QELEMS);
        float s = 0.f;
        #pragma unroll
        for (int i = 0; i < 16; ++i) {
            float4 v = ldg_el4(&xv[tid + i * 256], pol);
            s += (v.x + v.y) + (v.z + v.w);
        }
        #pragma unroll
        for (int o = 16; o; o >>= 1) s += __shfl_down_sync(0xffffffffu, s, o);
        if (lane == 0) ws[warp] = s;
        __syncthreads();
        if (tid == 0)
            g_part[item] = ws[0] + ws[1] + ws[2] + ws[3]
                         + ws[4] + ws[5] + ws[6] + ws[7];
        __syncthreads();
    }

    // ---- group-local release + wait (64 blocks only) -----------------------
    if (tid == 0) {
        __threadfence();
        atomicAdd(&g_done[g], 4u);
        while (*((volatile unsigned int*)&g_done[g]) < target)
            __nanosleep(32);
    }
    __syncthreads();
    __threadfence();

    // ---- lf weights + per-channel constants (all 4 k at once) --------------
    if (tid < C_) {
        const float* p = g_part + (g * C_ + tid) * 4;
        ps[tid] = (__ldcg(p) + __ldcg(p + 1) + __ldcg(p + 2) + __ldcg(p + 3))
                  * (1.f / (H_ * W_));
    }
    __syncthreads();
    if (tid < 36) {
        const int k  = tid / 9;
        const int t9 = tid - 9 * k;
        const int c  = (r >> 2) + 16 * k;
        const int jj = (c >> 3) * K2_ + t9;
        const float* wv = conv_w + jj * C_;
        float acc = 0.f;
        #pragma unroll
        for (int cc = 0; cc < C_; ++cc) acc = fmaf(ps[cc], wv[cc], acc);
        const float inv = rsqrtf(bn_var[jj] + 1e-5f);
        const float v = (acc - bn_mean[jj]) * (bn_gamma[jj] * inv) + bn_beta[jj];
        wlf[k][t9] = tanhf(v);
        if (t9 == 0) {
            const float ll  = __ldg(lamb_l + c);
            const float ia  = __ldg(inside_all + c);
            cst[k][0] = (ia + 1.f) * ll;          // A
            cst[k][1] = -ia * ps[c] * ll;         // Bc
            cst[k][2] = __ldg(lamb_h + c) + 1.f;  // lh1
        }
    }
    __syncthreads();

    // ---- 4 stencil tiles, LIFO over pooled quarters (k = 3..0) -------------
    const int tile = r & 3;
    #pragma unroll 1
    for (int k = 3; k >= 0; --k) {
        const int c     = (r >> 2) + 16 * k;
        const int plane = g * C_ + c;
        stencil_tile(x, out, plane, tile, warp, lane, pol,
                     wlf[k], cst[k][0], cst[k][1], cst[k][2]);
    }
}

// ---------------------------------------------------------------------------
extern "C" void kernel_launch(void* const* d_in, const int* in_sizes, int n_in,
                              void* d_out, int out_size) {
    const float* x          = (const float*)d_in[0];
    const float* conv_w     = (const float*)d_in[1];
    const float* bn_gamma   = (const float*)d_in[2];
    const float* bn_beta    = (const float*)d_in[3];
    const float* bn_mean    = (const float*)d_in[4];
    const float* bn_var     = (const float*)d_in[5];
    const float* lamb_l     = (const float*)d_in[6];
    const float* lamb_h     = (const float*)d_in[7];
    const float* inside_all = (const float*)d_in[8];
    float* out = (float*)d_out;

    fused_kernel<<<NBLK, 256>>>(x, conv_w, bn_gamma, bn_beta, bn_mean, bn_var,
                                lamb_l, lamb_h, inside_all, out);
}